// round 2
// baseline (speedup 1.0000x reference)
#include <cuda_runtime.h>

#define LOG2E 1.4426950408889634f
#define BLK 256

__device__ __forceinline__ float ex2f(float x) {
    float y; asm("ex2.approx.f32 %0, %1;" : "=f"(y) : "f"(x)); return y;
}
__device__ __forceinline__ float rcpf(float x) {
    float y; asm("rcp.approx.f32 %0, %1;" : "=f"(y) : "f"(x)); return y;
}

__global__ __launch_bounds__(BLK)
void logic_kernel(const float* __restrict__ state,
                  const float* __restrict__ c_templates,
                  const float* __restrict__ c_gammas,
                  const float* __restrict__ a_templates,
                  const float* __restrict__ a_gammas,
                  const float* __restrict__ a_body_W,
                  const float* __restrict__ a_body_b,
                  const float* __restrict__ a_head_W,
                  const float* __restrict__ a_head_b,
                  const float* __restrict__ act_W,
                  const float* __restrict__ act_b,
                  float* __restrict__ out, int B)
{
    // ---- weights staged in shared (broadcast reads in the hot loops) ----
    __shared__ float s_ct[24];   // concrete templates [12][2]
    __shared__ float s_cw[24];   // (1 - clip(gamma)) * log2(e)  [12][2]
    __shared__ float s_at[24];   // abstraction templates [6][2][2]
    __shared__ float s_aw[24];   // (1 - clip(gamma)) * log2(e)  [6][2][2]
    __shared__ float s_bW[96];   // body W [6][2][4][2]
    __shared__ float s_bb[48];   // body b [6][2][4]
    __shared__ float s_hW[48];   // head W [6][2][4]
    __shared__ float s_hb[12];   // head b [6][2]
    __shared__ float s_aWt[108]; // action W [9][12]
    __shared__ float s_ab[9];    // action b [9]
    // input staging padded to stride 19 (coprime with 32 banks); reused for output
    __shared__ float s_io[BLK * 19];

    const int t = threadIdx.x;
    if (t < 24) {
        s_ct[t] = c_templates[t];
        s_cw[t] = (1.0f - __saturatef(c_gammas[t])) * LOG2E;
        s_at[t] = a_templates[t];
        s_aw[t] = (1.0f - __saturatef(a_gammas[t])) * LOG2E;
    }
    if (t < 96)  s_bW[t] = a_body_W[t];
    if (t < 48)  { s_bb[t] = a_body_b[t]; s_hW[t] = a_head_W[t]; }
    if (t < 12)  s_hb[t] = a_head_b[t];
    if (t < 108) s_aWt[t] = act_W[t];
    if (t < 9)   s_ab[t]  = act_b[t];

    // ---- coalesced scalar input staging: 256 rows x 18 floats ----
    const long long in_base = (long long)blockIdx.x * (BLK * 18);
    const long long in_lim  = (long long)B * 18;
    #pragma unroll
    for (int k = t; k < BLK * 18; k += BLK) {
        long long g = in_base + k;
        float v = (g < in_lim) ? __ldg(&state[g]) : 0.0f;
        s_io[(k / 18) * 19 + (k % 18)] = v;
    }
    __syncthreads();

    const int row = blockIdx.x * BLK + t;
    float qv[9];

    if (row < B) {
        // ---- load board: 9 squares x 2 features (conflict-free, stride 19) ----
        float b0[9], b1[9];
        const float* my = &s_io[t * 19];
        #pragma unroll
        for (int i = 0; i < 9; i++) { b0[i] = my[2*i]; b1[i] = my[2*i + 1]; }

        // ---- ConcreteLayer: 12 rules, softmax over 9 squares ----
        float cf0[12], cf1[12];
        #pragma unroll
        for (int r = 0; r < 12; r++) {
            const float t0 = s_ct[2*r], t1 = s_ct[2*r+1];
            const float w0 = s_cw[2*r], w1 = s_cw[2*r+1];   // pre-scaled by log2e
            float ms[9];
            float mn = 3.4e38f;
            #pragma unroll
            for (int i = 0; i < 9; i++) {
                float d0 = t0 - b0[i];
                float d1 = t1 - b1[i];
                float m  = (w0 * d0) * d0;
                m = fmaf(w1 * d1, d1, m);
                ms[i] = m;
                mn = fminf(mn, m);
            }
            float sum = 0.0f, wsum = 0.0f;
            #pragma unroll
            for (int i = 0; i < 9; i++) {
                float e = ex2f(mn - ms[i]);      // exp(min - ms) in base-2 domain
                sum  += e;
                wsum  = fmaf(e, b1[i], wsum);
            }
            cf0[r] = ex2f(-mn);                  // pattern_strength = exp(-min ms)
            cf1[r] = wsum * rcpf(sum);           // matched[..., 1]
        }

        // ---- AbstractionLayer: 6 rules x 2 clauses, softmax over 12 ----
        float conc[12];
        #pragma unroll
        for (int r = 0; r < 6; r++) {
            float cap[4] = {0.f, 0.f, 0.f, 0.f};
            #pragma unroll
            for (int j = 0; j < 2; j++) {
                const int rj = r*2 + j;
                const float at0 = s_at[2*rj], at1 = s_at[2*rj+1];
                const float aw0 = s_aw[2*rj], aw1 = s_aw[2*rj+1];   // pre-scaled
                float ms[12];
                float mn = 3.4e38f;
                #pragma unroll
                for (int i = 0; i < 12; i++) {
                    float d0 = at0 - cf0[i];
                    float d1 = at1 - cf1[i];
                    float m  = (aw0 * d0) * d0;
                    m = fmaf(aw1 * d1, d1, m);
                    ms[i] = m;
                    mn = fminf(mn, m);
                }
                float sum = 0.f, sl0 = 0.f, sl1 = 0.f;
                #pragma unroll
                for (int i = 0; i < 12; i++) {
                    float e = ex2f(mn - ms[i]);
                    sum += e;
                    sl0 = fmaf(e, cf0[i], sl0);
                    sl1 = fmaf(e, cf1[i], sl1);
                }
                float inv = rcpf(sum);
                float sel0 = sl0 * inv;
                float sel1 = sl1 * inv;
                #pragma unroll
                for (int v = 0; v < 4; v++) {
                    float val = fmaf(s_bW[((rj)*4 + v)*2 + 0], sel0,
                               fmaf(s_bW[((rj)*4 + v)*2 + 1], sel1,
                                    s_bb[(rj)*4 + v]));
                    cap[v] += val;
                }
            }
            #pragma unroll
            for (int l = 0; l < 2; l++) {
                float c = s_hb[r*2 + l];
                #pragma unroll
                for (int v = 0; v < 4; v++)
                    c = fmaf(cap[v], s_hW[(r*2 + l)*4 + v], c);
                conc[r*2 + l] = c;
            }
        }

        // ---- ActionLayer: q = conc(12) @ W.T + b ----
        #pragma unroll
        for (int k = 0; k < 9; k++) {
            float q = s_ab[k];
            #pragma unroll
            for (int m = 0; m < 12; m++)
                q = fmaf(s_aWt[k*12 + m], conc[m], q);
            qv[k] = q;
        }
    }

    // ---- reuse s_io as output staging (stride 9, coprime with 32 -> no conflicts) ----
    __syncthreads();
    if (row < B) {
        #pragma unroll
        for (int k = 0; k < 9; k++) s_io[t*9 + k] = qv[k];
    }
    __syncthreads();

    // ---- coalesced scalar store: block's 256x9 floats contiguous ----
    const long long out_base = (long long)blockIdx.x * (BLK * 9);
    const long long out_lim  = (long long)B * 9;
    #pragma unroll
    for (int k = t; k < BLK * 9; k += BLK) {
        long long g = out_base + k;
        if (g < out_lim) out[g] = s_io[k];
    }
}

extern "C" void kernel_launch(void* const* d_in, const int* in_sizes, int n_in,
                              void* d_out, int out_size) {
    const float* state       = (const float*)d_in[0];
    const float* c_templates = (const float*)d_in[1];
    const float* c_gammas    = (const float*)d_in[2];
    const float* a_templates = (const float*)d_in[3];
    const float* a_gammas    = (const float*)d_in[4];
    const float* a_body_W    = (const float*)d_in[5];
    const float* a_body_b    = (const float*)d_in[6];
    const float* a_head_W    = (const float*)d_in[7];
    const float* a_head_b    = (const float*)d_in[8];
    const float* act_W       = (const float*)d_in[9];
    const float* act_b       = (const float*)d_in[10];
    float* out = (float*)d_out;

    const int B = in_sizes[0] / 18;
    const int grid = (B + BLK - 1) / BLK;
    logic_kernel<<<grid, BLK>>>(state, c_templates, c_gammas, a_templates,
                                a_gammas, a_body_W, a_body_b, a_head_W,
                                a_head_b, act_W, act_b, out, B);
}